// round 4
// baseline (speedup 1.0000x reference)
#include <cuda_runtime.h>
#include <cstddef>
#include <math_constants.h>

#define B_DIM 4096
#define K_DIM 64
#define D_DIM 512
#define N_AGENTS 64
#define NEG_INF -1e9f
#define THREADS 512
#define NWARP 16

__global__ __launch_bounds__(THREADS, 2)
void block_diag_agg_kernel(const float* __restrict__ h,
                           const float* __restrict__ keys,
                           const int* __restrict__ sigma,
                           float* __restrict__ out) {
    __shared__ float s_m[NWARP];
    __shared__ float s_s[NWARP];
    __shared__ float s_fac[NWARP];
    __shared__ float s_stage[NWARP][D_DIM];   // 32 KB

    const int b    = blockIdx.x;
    const int tid  = threadIdx.x;
    const int warp = tid >> 5;
    const int lane = tid & 31;

    const float* hb = h + (size_t)b * (K_DIM * D_DIM);
    const int*   sb = sigma + (size_t)b * K_DIM;

    // ---- Single pass: per-warp online softmax over 4 owned k-slots ----
    int sid[4];
    #pragma unroll
    for (int i = 0; i < 4; i++) sid[i] = sb[warp * 4 + i];

    float m = -CUDART_INF_F;
    float s = 0.0f;
    float4 acc0 = make_float4(0.f, 0.f, 0.f, 0.f);
    float4 acc1 = make_float4(0.f, 0.f, 0.f, 0.f);
    float4 acc2 = make_float4(0.f, 0.f, 0.f, 0.f);
    float4 acc3 = make_float4(0.f, 0.f, 0.f, 0.f);

    #pragma unroll
    for (int i = 0; i < 4; i++) {
        const int k = warp * 4 + i;
        const bool valid = (sid[i] < N_AGENTS);
        const float4* hrow = (const float4*)(hb + (size_t)k * D_DIM);
        const float4* krow = (const float4*)(keys + (size_t)(valid ? sid[i] : 0) * D_DIM);

        float4 hv0 = __ldcg(&hrow[lane +  0]);
        float4 hv1 = __ldcg(&hrow[lane + 32]);
        float4 hv2 = __ldcg(&hrow[lane + 64]);
        float4 hv3 = __ldcg(&hrow[lane + 96]);
        float4 kv0 = __ldg(&krow[lane +  0]);
        float4 kv1 = __ldg(&krow[lane + 32]);
        float4 kv2 = __ldg(&krow[lane + 64]);
        float4 kv3 = __ldg(&krow[lane + 96]);

        float dot = 0.0f;
        dot = fmaf(hv0.x, kv0.x, dot); dot = fmaf(hv0.y, kv0.y, dot);
        dot = fmaf(hv0.z, kv0.z, dot); dot = fmaf(hv0.w, kv0.w, dot);
        dot = fmaf(hv1.x, kv1.x, dot); dot = fmaf(hv1.y, kv1.y, dot);
        dot = fmaf(hv1.z, kv1.z, dot); dot = fmaf(hv1.w, kv1.w, dot);
        dot = fmaf(hv2.x, kv2.x, dot); dot = fmaf(hv2.y, kv2.y, dot);
        dot = fmaf(hv2.z, kv2.z, dot); dot = fmaf(hv2.w, kv2.w, dot);
        dot = fmaf(hv3.x, kv3.x, dot); dot = fmaf(hv3.y, kv3.y, dot);
        dot = fmaf(hv3.z, kv3.z, dot); dot = fmaf(hv3.w, kv3.w, dot);

        #pragma unroll
        for (int off = 16; off > 0; off >>= 1)
            dot += __shfl_xor_sync(0xFFFFFFFFu, dot, off);

        const float logit = valid ? dot : NEG_INF;
        const float m_new = fmaxf(m, logit);
        const float scale = __expf(m - m_new);     // iter 0: exp(-inf) = 0
        const float p     = __expf(logit - m_new);
        s = fmaf(s, scale, p);
        m = m_new;

        acc0.x = fmaf(acc0.x, scale, p * hv0.x);
        acc0.y = fmaf(acc0.y, scale, p * hv0.y);
        acc0.z = fmaf(acc0.z, scale, p * hv0.z);
        acc0.w = fmaf(acc0.w, scale, p * hv0.w);
        acc1.x = fmaf(acc1.x, scale, p * hv1.x);
        acc1.y = fmaf(acc1.y, scale, p * hv1.y);
        acc1.z = fmaf(acc1.z, scale, p * hv1.z);
        acc1.w = fmaf(acc1.w, scale, p * hv1.w);
        acc2.x = fmaf(acc2.x, scale, p * hv2.x);
        acc2.y = fmaf(acc2.y, scale, p * hv2.y);
        acc2.z = fmaf(acc2.z, scale, p * hv2.z);
        acc2.w = fmaf(acc2.w, scale, p * hv2.w);
        acc3.x = fmaf(acc3.x, scale, p * hv3.x);
        acc3.y = fmaf(acc3.y, scale, p * hv3.y);
        acc3.z = fmaf(acc3.z, scale, p * hv3.z);
        acc3.w = fmaf(acc3.w, scale, p * hv3.w);
    }

    if (lane == 0) { s_m[warp] = m; s_s[warp] = s; }
    __syncthreads();

    // ---- Merge the 16 per-warp softmax states (warp 0) ----
    if (warp == 0) {
        float mw = (lane < NWARP) ? s_m[lane] : -CUDART_INF_F;
        float sw = (lane < NWARP) ? s_s[lane] : 0.0f;
        float mg = mw;
        #pragma unroll
        for (int off = 16; off > 0; off >>= 1)
            mg = fmaxf(mg, __shfl_xor_sync(0xFFFFFFFFu, mg, off));
        float e = __expf(mw - mg);                 // lanes >=16: exp(-inf)=0
        float contrib = e * sw;
        float S = contrib;
        #pragma unroll
        for (int off = 16; off > 0; off >>= 1)
            S += __shfl_xor_sync(0xFFFFFFFFu, S, off);
        if (lane < NWARP) s_fac[lane] = e / S;
    }
    __syncthreads();

    // ---- Stage scaled per-warp partials, then tree-sum across warps ----
    const float f = s_fac[warp];
    float4* stp = (float4*)&s_stage[warp][0];
    stp[lane +  0] = make_float4(acc0.x * f, acc0.y * f, acc0.z * f, acc0.w * f);
    stp[lane + 32] = make_float4(acc1.x * f, acc1.y * f, acc1.z * f, acc1.w * f);
    stp[lane + 64] = make_float4(acc2.x * f, acc2.y * f, acc2.z * f, acc2.w * f);
    stp[lane + 96] = make_float4(acc3.x * f, acc3.y * f, acc3.z * f, acc3.w * f);
    __syncthreads();

    float outv = 0.0f;
    #pragma unroll
    for (int w = 0; w < NWARP; w++)
        outv += s_stage[w][tid];
    out[(size_t)b * D_DIM + tid] = outv;
}

extern "C" void kernel_launch(void* const* d_in, const int* in_sizes, int n_in,
                              void* d_out, int out_size) {
    const float* h     = (const float*)d_in[0];
    const float* keys  = (const float*)d_in[1];
    const int*   sigma = (const int*)d_in[2];
    float*       out   = (float*)d_out;

    block_diag_agg_kernel<<<B_DIM, THREADS>>>(h, keys, sigma, out);
}

// round 5
// speedup vs baseline: 1.0346x; 1.0346x over previous
#include <cuda_runtime.h>
#include <cstddef>

#define B_DIM 4096
#define K_DIM 64
#define D_DIM 512
#define N_AGENTS 64
#define NEG_INF -1e9f
#define THREADS 512

__global__ __launch_bounds__(THREADS, 3)
void block_diag_agg_kernel(const float* __restrict__ h,
                           const float* __restrict__ keys,
                           const int* __restrict__ sigma,
                           float* __restrict__ out) {
    __shared__ float  s_logits[K_DIM];
    __shared__ float  s_alpha[K_DIM];
    __shared__ float4 s_part[4][D_DIM / 4];   // 8 KB partial pooling sums

    const int b    = blockIdx.x;
    const int tid  = threadIdx.x;
    const int warp = tid >> 5;
    const int lane = tid & 31;

    const float* hb = h + (size_t)b * (K_DIM * D_DIM);
    const int*   sb = sigma + (size_t)b * K_DIM;

    // ---- Phase 1: per-slot dot products. 16 warps x 4 k-slots. ----
    #pragma unroll
    for (int i = 0; i < 4; i++) {
        const int k = warp * 4 + i;
        const int sid    = sb[k];
        const bool valid = (sid < N_AGENTS);
        const float4* hrow = (const float4*)(hb + (size_t)k * D_DIM);
        const float4* krow = (const float4*)(keys + (size_t)(valid ? sid : 0) * D_DIM);

        float acc = 0.0f;
        #pragma unroll
        for (int j = 0; j < 4; j++) {
            const int idx = lane + 32 * j;            // 0..127 float4 per row
            float4 hv = __ldcg(&hrow[idx]);           // stream: don't pollute L1
            float4 kv = __ldg(&krow[idx]);            // keys L1-resident
            acc = fmaf(hv.x, kv.x, acc);
            acc = fmaf(hv.y, kv.y, acc);
            acc = fmaf(hv.z, kv.z, acc);
            acc = fmaf(hv.w, kv.w, acc);
        }
        #pragma unroll
        for (int off = 16; off > 0; off >>= 1)
            acc += __shfl_xor_sync(0xFFFFFFFFu, acc, off);
        if (lane == 0)
            s_logits[k] = valid ? acc : NEG_INF;
    }
    __syncthreads();

    // ---- Phase 2: softmax over K=64 (warp 0 only) ----
    if (warp == 0) {
        float l0 = s_logits[lane];
        float l1 = s_logits[lane + 32];
        float m = fmaxf(l0, l1);
        #pragma unroll
        for (int off = 16; off > 0; off >>= 1)
            m = fmaxf(m, __shfl_xor_sync(0xFFFFFFFFu, m, off));
        float e0 = __expf(l0 - m);
        float e1 = __expf(l1 - m);
        float s = e0 + e1;
        #pragma unroll
        for (int off = 16; off > 0; off >>= 1)
            s += __shfl_xor_sync(0xFFFFFFFFu, s, off);
        float inv = 1.0f / s;
        s_alpha[lane]      = e0 * inv;
        s_alpha[lane + 32] = e1 * inv;
    }
    __syncthreads();

    // ---- Phase 3: vectorized pooling. Thread t owns (group g = t>>7, d4 = t&127).
    //      Group g accumulates k = 16g..16g+15; 16 independent LDG.128 (L2-hit). ----
    {
        const int g  = tid >> 7;        // 0..3
        const int d4 = tid & 127;       // float4 index over 512 dims
        const float4* hrow4 = (const float4*)hb + (size_t)(g * 16) * (D_DIM / 4) + d4;
        const float*  ap    = &s_alpha[g * 16];

        float4 acc = make_float4(0.f, 0.f, 0.f, 0.f);
        #pragma unroll
        for (int k = 0; k < 16; k++) {
            const float a  = ap[k];
            const float4 hv = __ldcg(hrow4 + (size_t)k * (D_DIM / 4));
            acc.x = fmaf(a, hv.x, acc.x);
            acc.y = fmaf(a, hv.y, acc.y);
            acc.z = fmaf(a, hv.z, acc.z);
            acc.w = fmaf(a, hv.w, acc.w);
        }
        s_part[g][d4] = acc;
    }
    __syncthreads();

    // ---- Final 4-way reduction + store: thread tid owns output dim d = tid ----
    {
        const float* p = (const float*)s_part;        // [4][512] floats
        float v = p[tid] + p[D_DIM + tid] + p[2 * D_DIM + tid] + p[3 * D_DIM + tid];
        out[(size_t)b * D_DIM + tid] = v;
    }
}

extern "C" void kernel_launch(void* const* d_in, const int* in_sizes, int n_in,
                              void* d_out, int out_size) {
    const float* h     = (const float*)d_in[0];
    const float* keys  = (const float*)d_in[1];
    const int*   sigma = (const int*)d_in[2];
    float*       out   = (float*)d_out;

    block_diag_agg_kernel<<<B_DIM, THREADS>>>(h, keys, sigma, out);
}